// round 11
// baseline (speedup 1.0000x reference)
#include <cuda_runtime.h>
#include <cuda_fp16.h>
#include <cuda_bf16.h>
#include <math.h>
#include <stdint.h>

#define NNODE 10000
#define NEDGE 320000
#define ETOT  (NEDGE + NNODE)
#define FIN   256
#define HH    8
#define CC    64
#define FOUT  512   /* HH*CC */
#define NEG   0.2f
#define NSPLIT 5056   /* 79 * 64: node/row-block aligned pipeline split */

// ---------------- static device scratch (no allocations allowed) ------------
__device__ __align__(16) __half g_hh[NNODE * FOUT];   // GEMM out fp16 (10.2MB)
__device__ float g_x2[NNODE * FOUT];      // layer-1 activated output (20.5 MB)
__device__ float g_als[2][NNODE * HH];    // att dots, one set per layer
__device__ float g_ald[2][NNODE * HH];
__device__ int   g_cnt[NNODE];
__device__ int   g_offs[NNODE + 1];
__device__ int   g_cursor[NNODE];
__device__ int2  g_edge[ETOT];            // dst-sorted CSR: (src, log2w-bits)

// ---------------- zero kernels ----------------------------------------------
__global__ void k_zero_att() {
    int i = blockIdx.x * blockDim.x + threadIdx.x;
    if (i < NNODE * HH) {
        g_als[0][i] = 0.f; g_ald[0][i] = 0.f;
        g_als[1][i] = 0.f; g_ald[1][i] = 0.f;
    }
}
__global__ void k_zero_cnt() {
    int i = blockIdx.x * blockDim.x + threadIdx.x;
    if (i < NNODE) g_cnt[i] = 0;
}
__global__ void k_hist(const int* __restrict__ ei) {
    int e = blockIdx.x * blockDim.x + threadIdx.x;
    if (e >= ETOT) return;
    int d = (e < NEDGE) ? ei[NEDGE + e] : (e - NEDGE);
    atomicAdd(&g_cnt[d], 1);
}
__global__ void k_scan() {
    __shared__ int sh[1024];
    int t = threadIdx.x;
    const int CH = (NNODE + 1023) / 1024;
    int base = t * CH;
    int s = 0;
    for (int i = 0; i < CH; i++) {
        int idx = base + i;
        if (idx < NNODE) s += g_cnt[idx];
    }
    sh[t] = s;
    __syncthreads();
    for (int off = 1; off < 1024; off <<= 1) {
        int v = (t >= off) ? sh[t - off] : 0;
        __syncthreads();
        sh[t] += v;
        __syncthreads();
    }
    int run = (t == 0) ? 0 : sh[t - 1];
    for (int i = 0; i < CH; i++) {
        int idx = base + i;
        if (idx < NNODE) {
            g_offs[idx]   = run;
            g_cursor[idx] = run;
            run += g_cnt[idx];
        }
    }
    if (t == 1023) g_offs[NNODE] = run;
}
__global__ void k_scatter(const int* __restrict__ ei, const float* __restrict__ ew) {
    int e = blockIdx.x * blockDim.x + threadIdx.x;
    if (e >= ETOT) return;
    int s, d; float lw;
    if (e < NEDGE) {
        s = ei[e]; d = ei[NEDGE + e];
        lw = log2f(ew[e]);
    } else {
        s = d = e - NEDGE;
        lw = 0.f;
    }
    int pos = atomicAdd(&g_cursor[d], 1);
    g_edge[pos] = make_int2(s, __float_as_int(lw));
}

// ---------------- 3xBF16 tensor-core GEMM + fused att-dot epilogue ----------
// 64x128 CTA tile (2 CTAs/SM), BK=16, coalesced fp32 loads, in-register
// hi/lo split, mma.m16n8k16.bf16 x3 products, double-buffered smem.
__device__ __forceinline__ uint32_t bf16x2(float odd, float even) {
    uint32_t r;
    asm("cvt.rn.bf16x2.f32 %0, %1, %2;" : "=r"(r) : "f"(odd), "f"(even));
    return r;
}
__device__ __forceinline__ void split2(float even, float odd,
                                       uint32_t& H, uint32_t& L) {
    H = bf16x2(odd, even);
    float eh = __uint_as_float(H << 16);
    float oh = __uint_as_float(H & 0xffff0000u);
    L = bf16x2(odd - oh, even - eh);
}
__device__ __forceinline__ void mma_bf16(float c[4],
                                         uint32_t a0, uint32_t a1, uint32_t a2, uint32_t a3,
                                         uint32_t b0, uint32_t b1) {
    asm volatile(
        "mma.sync.aligned.m16n8k16.row.col.f32.bf16.bf16.f32 "
        "{%0,%1,%2,%3}, {%4,%5,%6,%7}, {%8,%9}, {%0,%1,%2,%3};"
        : "+f"(c[0]), "+f"(c[1]), "+f"(c[2]), "+f"(c[3])
        : "r"(a0), "r"(a1), "r"(a2), "r"(a3), "r"(b0), "r"(b1));
}

#define APITCH 72    /* 72 mod 32 = 8 -> conflict-free A frag LDS */
#define BPITCH 136   /* 136 mod 32 = 8 -> conflict-free B frag LDS */

__global__ __launch_bounds__(256, 2) void k_gemm_tc(
    const float* __restrict__ A_ext, const float* __restrict__ B,
    const float* __restrict__ att_s, const float* __restrict__ att_d,
    int M, int K, int layer, int m0)
{
    __shared__ uint32_t AsH[2][8][APITCH];
    __shared__ uint32_t AsL[2][8][APITCH];
    __shared__ uint32_t BsH[2][8][BPITCH];
    __shared__ uint32_t BsL[2][8][BPITCH];

    const float* A = layer ? g_x2 : A_ext;
    float* als = g_als[layer];
    float* ald = g_ald[layer];
    const int NN = FOUT;

    int bm = m0 + blockIdx.y * 64;
    int bn = blockIdx.x * 128;
    int tid  = threadIdx.x;
    int lane = tid & 31;
    int warp = tid >> 5;
    int wm = (warp & 1) * 32;    // warp row offset (2 warp-rows)
    int wn = (warp >> 1) * 32;   // warp col offset (4 warp-cols)

    // A tile 64x16 fp32: row = tid>>2, k offset = (tid&3)*4 (one float4)
    int am = tid >> 2;
    int ak = (tid & 3) * 4;
    int arow = bm + am;
    // B tile 16x128 fp32: kpair row = tid>>5, cols (tid&31)*4
    int br = tid >> 5;
    int bc = (tid & 31) * 4;

    float acc[2][4][4];
#pragma unroll
    for (int mi = 0; mi < 2; mi++)
#pragma unroll
        for (int ni = 0; ni < 4; ni++)
#pragma unroll
            for (int r = 0; r < 4; r++) acc[mi][ni][r] = 0.f;

    float4 av, b0v, b1v;
    auto load_tile = [&](int k0) {
        av = (arow < M) ? *(const float4*)(A + (size_t)arow * K + k0 + ak)
                        : make_float4(0.f, 0.f, 0.f, 0.f);
        b0v = *(const float4*)(B + (size_t)(k0 + 2 * br) * NN + bn + bc);
        b1v = *(const float4*)(B + (size_t)(k0 + 2 * br + 1) * NN + bn + bc);
    };
    auto store_tile = [&](int buf) {
        int akp = ak >> 1;   // kpair base: 0,2,4,6
        uint32_t H0, L0, H1, L1;
        split2(av.x, av.y, H0, L0);
        split2(av.z, av.w, H1, L1);
        AsH[buf][akp][am]     = H0;  AsL[buf][akp][am]     = L0;
        AsH[buf][akp + 1][am] = H1;  AsL[buf][akp + 1][am] = L1;
        float ve[4] = {b0v.x, b0v.y, b0v.z, b0v.w};
        float vo[4] = {b1v.x, b1v.y, b1v.z, b1v.w};
        uint32_t BH[4], BL[4];
#pragma unroll
        for (int j = 0; j < 4; j++) split2(ve[j], vo[j], BH[j], BL[j]);
        *(uint4*)&BsH[buf][br][bc] = make_uint4(BH[0], BH[1], BH[2], BH[3]);
        *(uint4*)&BsL[buf][br][bc] = make_uint4(BL[0], BL[1], BL[2], BL[3]);
    };

    load_tile(0);
    store_tile(0);
    __syncthreads();

    int buf = 0;
    for (int k0 = 0; k0 < K; k0 += 16) {
        bool has_next = (k0 + 16) < K;
        if (has_next) load_tile(k0 + 16);

        int fk = lane & 3;
        int fg = lane >> 2;
        uint32_t ah[2][4], al[2][4];
#pragma unroll
        for (int mi = 0; mi < 2; mi++) {
            int m0f = wm + mi * 16 + fg;
            ah[mi][0] = AsH[buf][fk][m0f];      ah[mi][1] = AsH[buf][fk][m0f + 8];
            ah[mi][2] = AsH[buf][fk + 4][m0f];  ah[mi][3] = AsH[buf][fk + 4][m0f + 8];
            al[mi][0] = AsL[buf][fk][m0f];      al[mi][1] = AsL[buf][fk][m0f + 8];
            al[mi][2] = AsL[buf][fk + 4][m0f];  al[mi][3] = AsL[buf][fk + 4][m0f + 8];
        }
        uint32_t bh[4][2], bl[4][2];
#pragma unroll
        for (int ni = 0; ni < 4; ni++) {
            int n0 = wn + ni * 8 + fg;
            bh[ni][0] = BsH[buf][fk][n0];      bh[ni][1] = BsH[buf][fk + 4][n0];
            bl[ni][0] = BsL[buf][fk][n0];      bl[ni][1] = BsL[buf][fk + 4][n0];
        }

#pragma unroll
        for (int mi = 0; mi < 2; mi++)
#pragma unroll
            for (int ni = 0; ni < 4; ni++) {
                mma_bf16(acc[mi][ni], ah[mi][0], ah[mi][1], ah[mi][2], ah[mi][3],
                         bh[ni][0], bh[ni][1]);
                mma_bf16(acc[mi][ni], ah[mi][0], ah[mi][1], ah[mi][2], ah[mi][3],
                         bl[ni][0], bl[ni][1]);
                mma_bf16(acc[mi][ni], al[mi][0], al[mi][1], al[mi][2], al[mi][3],
                         bh[ni][0], bh[ni][1]);
            }

        if (has_next) store_tile(buf ^ 1);
        __syncthreads();
        buf ^= 1;
    }

    // ---- epilogue: fp16 store + fused att dot products ----
    int fg = lane >> 2;
    int fk = lane & 3;
    int headg = (bn + wn) >> 6;

    float vsv[4][2], vdv[4][2];
#pragma unroll
    for (int ni = 0; ni < 4; ni++) {
        int c = bn + wn + ni * 8 + fk * 2;
        vsv[ni][0] = att_s[c]; vsv[ni][1] = att_s[c + 1];
        vdv[ni][0] = att_d[c]; vdv[ni][1] = att_d[c + 1];
    }

#pragma unroll
    for (int mi = 0; mi < 2; mi++) {
        int r0 = bm + wm + mi * 16 + fg;
        int r1 = r0 + 8;
        float s0 = 0.f, d0 = 0.f, s1 = 0.f, d1 = 0.f;
#pragma unroll
        for (int ni = 0; ni < 4; ni++) {
            int col = bn + wn + ni * 8 + fk * 2;
            __half2 h01 = __floats2half2_rn(acc[mi][ni][0], acc[mi][ni][1]);
            __half2 h23 = __floats2half2_rn(acc[mi][ni][2], acc[mi][ni][3]);
            if (r0 < M) *(__half2*)(g_hh + (size_t)r0 * NN + col) = h01;
            if (r1 < M) *(__half2*)(g_hh + (size_t)r1 * NN + col) = h23;
            s0 += acc[mi][ni][0] * vsv[ni][0] + acc[mi][ni][1] * vsv[ni][1];
            d0 += acc[mi][ni][0] * vdv[ni][0] + acc[mi][ni][1] * vdv[ni][1];
            s1 += acc[mi][ni][2] * vsv[ni][0] + acc[mi][ni][3] * vsv[ni][1];
            d1 += acc[mi][ni][2] * vdv[ni][0] + acc[mi][ni][3] * vdv[ni][1];
        }
#pragma unroll
        for (int off = 2; off; off >>= 1) {
            s0 += __shfl_xor_sync(0xffffffffu, s0, off);
            d0 += __shfl_xor_sync(0xffffffffu, d0, off);
            s1 += __shfl_xor_sync(0xffffffffu, s1, off);
            d1 += __shfl_xor_sync(0xffffffffu, d1, off);
        }
        if (fk == 0) {
            if (r0 < M) {
                atomicAdd(&als[r0 * HH + headg], s0);
                atomicAdd(&ald[r0 * HH + headg], d0);
            }
            if (r1 < M) {
                atomicAdd(&als[r1 * HH + headg], s1);
                atomicAdd(&ald[r1 * HH + headg], d1);
            }
        }
    }
}

// ------------- fused flash softmax + aggregation: warp = (node, head) -------
__global__ void k_fusedagg(const float* __restrict__ bias,
                           float* __restrict__ out_ext, int do_relu, int layer,
                           int n0)
{
    int n = n0 + blockIdx.x;
    int w = threadIdx.x >> 5, lane = threadIdx.x & 31;
    float* out = out_ext ? out_ext : g_x2;
    const float* als = g_als[layer];
    int s0 = g_offs[n], s1 = g_offs[n + 1];

    float adw = g_ald[layer][n * HH + w];
    float m = -1e30f, ssum = 0.f, accx = 0.f, accy = 0.f;

    for (int base = s0; base < s1; base += 32) {
        int idx = base + lane;
        bool valid = idx < s1;
        int2 e2 = valid ? g_edge[idx] : make_int2(0, 0);
        int mys = e2.x;
        float t = -1e30f;
        if (valid) {
            float a = als[mys * HH + w] + adw;
            a = (a > 0.f) ? a : NEG * a;   // leaky_relu
            t = a + __int_as_float(e2.y);
        }
        float cm = t;
#pragma unroll
        for (int o = 16; o; o >>= 1)
            cm = fmaxf(cm, __shfl_xor_sync(0xffffffffu, cm, o));
        float mnew = fmaxf(m, cm);
        float scale = __expf(m - mnew);
        ssum *= scale; accx *= scale; accy *= scale;
        m = mnew;

        float e = __expf(t - mnew);   // exactly 0 for invalid lanes
        ssum += e;

        int cnt = min(32, s1 - base);
        const __half* hrow_base = g_hh + w * CC + lane * 2;
        for (int jb = 0; jb < cnt; jb += 8) {
            float wv[8];
            float2 hv[8];
#pragma unroll
            for (int u = 0; u < 8; u++) {
                int j = (jb + u) & 31;
                int   s  = __shfl_sync(0xffffffffu, mys, j);
                wv[u]    = __shfl_sync(0xffffffffu, e, j);
                hv[u] = __half22float2(
                    *(const __half2*)(hrow_base + (size_t)s * FOUT));
            }
#pragma unroll
            for (int u = 0; u < 8; u++) {
                accx = fmaf(wv[u], hv[u].x, accx);
                accy = fmaf(wv[u], hv[u].y, accy);
            }
        }
    }
#pragma unroll
    for (int o = 16; o; o >>= 1)
        ssum += __shfl_xor_sync(0xffffffffu, ssum, o);

    float r = 1.f / ssum;
    float2 b = *(const float2*)(bias + w * CC + lane * 2);
    float ox = fmaf(accx, r, b.x);
    float oy = fmaf(accy, r, b.y);
    if (do_relu) { ox = fmaxf(ox, 0.f); oy = fmaxf(oy, 0.f); }
    *(float2*)(out + (size_t)n * FOUT + w * CC + lane * 2) = make_float2(ox, oy);
}

// ---------------- launch -----------------------------------------------------
extern "C" void kernel_launch(void* const* d_in, const int* in_sizes, int n_in,
                              void* d_out, int out_size)
{
    const float* x   = (const float*)d_in[0];
    const int*   ei  = (const int*)  d_in[1];
    const float* ew  = (const float*)d_in[2];
    const float* W1  = (const float*)d_in[3];
    const float* as1 = (const float*)d_in[4];
    const float* ad1 = (const float*)d_in[5];
    const float* b1  = (const float*)d_in[6];
    const float* W2  = (const float*)d_in[7];
    const float* as2 = (const float*)d_in[8];
    const float* ad2 = (const float*)d_in[9];
    const float* b2  = (const float*)d_in[10];
    float* out = (float*)d_out;

    // host-side stream/event setup (once; no device allocations)
    static cudaStream_t s2 = nullptr;
    static cudaEvent_t evFork, evCsr, evA1a, evA1b, evG2;
    if (!s2) {
        cudaStreamCreateWithFlags(&s2, cudaStreamNonBlocking);
        cudaEventCreateWithFlags(&evFork, cudaEventDisableTiming);
        cudaEventCreateWithFlags(&evCsr, cudaEventDisableTiming);
        cudaEventCreateWithFlags(&evA1a, cudaEventDisableTiming);
        cudaEventCreateWithFlags(&evA1b, cudaEventDisableTiming);
        cudaEventCreateWithFlags(&evG2, cudaEventDisableTiming);
    }

    // fork: CSR build chain runs concurrently with layer-1 GEMM
    cudaEventRecord(evFork, 0);
    cudaStreamWaitEvent(s2, evFork, 0);
    k_zero_cnt<<<(NNODE + 255) / 256, 256, 0, s2>>>();
    k_hist<<<(ETOT + 255) / 256, 256, 0, s2>>>(ei);
    k_scan<<<1, 1024, 0, s2>>>();
    k_scatter<<<(ETOT + 255) / 256, 256, 0, s2>>>(ei, ew);
    cudaEventRecord(evCsr, s2);

    // main: zero att accumulators, then layer-1 GEMM (all rows)
    k_zero_att<<<(NNODE * HH + 255) / 256, 256>>>();
    k_gemm_tc<<<dim3(4, (NNODE + 63) / 64), 256>>>(x, W1, as1, ad1,
                                                   NNODE, FIN, 0, 0);

    // join CSR, then pipelined agg1 halves
    cudaStreamWaitEvent(0, evCsr, 0);
    k_fusedagg<<<NSPLIT, 256>>>(b1, nullptr, 1, 0, 0);          // nodes [0,5056)
    cudaEventRecord(evA1a, 0);
    k_fusedagg<<<NNODE - NSPLIT, 256>>>(b1, nullptr, 1, 0, NSPLIT);
    cudaEventRecord(evA1b, 0);

    // layer-2 GEMM halves on s2, overlapping agg1b with gemm2a
    cudaStreamWaitEvent(s2, evA1a, 0);
    k_gemm_tc<<<dim3(4, NSPLIT / 64), 256, 0, s2>>>(nullptr, W2, as2, ad2,
                                                    NNODE, FOUT, 1, 0);
    cudaStreamWaitEvent(s2, evA1b, 0);
    k_gemm_tc<<<dim3(4, (NNODE - NSPLIT + 63) / 64), 256, 0, s2>>>(
        nullptr, W2, as2, ad2, NNODE, FOUT, 1, NSPLIT);
    cudaEventRecord(evG2, s2);

    // final aggregation needs all of layer-2 GEMM
    cudaStreamWaitEvent(0, evG2, 0);
    k_fusedagg<<<NNODE, 256>>>(b2, out, 0, 1, 0);               // -> d_out
}

// round 12
// speedup vs baseline: 1.0585x; 1.0585x over previous
#include <cuda_runtime.h>
#include <cuda_fp16.h>
#include <cuda_bf16.h>
#include <math.h>
#include <stdint.h>

#define NNODE 10000
#define NEDGE 320000
#define ETOT  (NEDGE + NNODE)
#define FIN   256
#define HH    8
#define CC    64
#define FOUT  512   /* HH*CC */
#define NEG   0.2f

// ---------------- static device scratch (no allocations allowed) ------------
__device__ __align__(16) __half g_hh[NNODE * FOUT];   // GEMM out fp16 (10.2MB)
__device__ float g_x2[NNODE * FOUT];      // layer-1 activated output (20.5 MB)
__device__ float g_als[2][NNODE * HH];    // att dots, one set per layer
__device__ float g_ald[2][NNODE * HH];
__device__ int   g_cnt[NNODE];
__device__ int   g_offs[NNODE + 1];
__device__ int   g_cursor[NNODE];
__device__ int2  g_edge[ETOT];            // dst-sorted CSR: (src, log2w-bits)

// ---------------- zero kernels ----------------------------------------------
__global__ void k_zero_att() {
    int i = blockIdx.x * blockDim.x + threadIdx.x;
    if (i < NNODE * HH) {
        g_als[0][i] = 0.f; g_ald[0][i] = 0.f;
        g_als[1][i] = 0.f; g_ald[1][i] = 0.f;
    }
}
__global__ void k_zero_cnt() {
    int i = blockIdx.x * blockDim.x + threadIdx.x;
    if (i < NNODE) g_cnt[i] = 0;
}
__global__ void k_hist(const int* __restrict__ ei) {
    int e = blockIdx.x * blockDim.x + threadIdx.x;
    if (e >= ETOT) return;
    int d = (e < NEDGE) ? ei[NEDGE + e] : (e - NEDGE);
    atomicAdd(&g_cnt[d], 1);
}
__global__ void k_scan() {
    __shared__ int sh[1024];
    int t = threadIdx.x;
    const int CH = (NNODE + 1023) / 1024;
    int base = t * CH;
    int s = 0;
    for (int i = 0; i < CH; i++) {
        int idx = base + i;
        if (idx < NNODE) s += g_cnt[idx];
    }
    sh[t] = s;
    __syncthreads();
    for (int off = 1; off < 1024; off <<= 1) {
        int v = (t >= off) ? sh[t - off] : 0;
        __syncthreads();
        sh[t] += v;
        __syncthreads();
    }
    int run = (t == 0) ? 0 : sh[t - 1];
    for (int i = 0; i < CH; i++) {
        int idx = base + i;
        if (idx < NNODE) {
            g_offs[idx]   = run;
            g_cursor[idx] = run;
            run += g_cnt[idx];
        }
    }
    if (t == 1023) g_offs[NNODE] = run;
}
__global__ void k_scatter(const int* __restrict__ ei, const float* __restrict__ ew) {
    int e = blockIdx.x * blockDim.x + threadIdx.x;
    if (e >= ETOT) return;
    int s, d; float lw;
    if (e < NEDGE) {
        s = ei[e]; d = ei[NEDGE + e];
        lw = log2f(ew[e]);
    } else {
        s = d = e - NEDGE;
        lw = 0.f;
    }
    int pos = atomicAdd(&g_cursor[d], 1);
    g_edge[pos] = make_int2(s, __float_as_int(lw));
}

// ---------------- 3xBF16 tensor-core GEMM + fused att-dot epilogue ----------
// 64x128 CTA tile (2 CTAs/SM), BK=16, coalesced fp32 loads, in-register
// hi/lo split, mma.m16n8k16.bf16 x3 products, double-buffered smem.
__device__ __forceinline__ uint32_t bf16x2(float odd, float even) {
    uint32_t r;
    asm("cvt.rn.bf16x2.f32 %0, %1, %2;" : "=r"(r) : "f"(odd), "f"(even));
    return r;
}
__device__ __forceinline__ void split2(float even, float odd,
                                       uint32_t& H, uint32_t& L) {
    H = bf16x2(odd, even);
    float eh = __uint_as_float(H << 16);
    float oh = __uint_as_float(H & 0xffff0000u);
    L = bf16x2(odd - oh, even - eh);
}
__device__ __forceinline__ void mma_bf16(float c[4],
                                         uint32_t a0, uint32_t a1, uint32_t a2, uint32_t a3,
                                         uint32_t b0, uint32_t b1) {
    asm volatile(
        "mma.sync.aligned.m16n8k16.row.col.f32.bf16.bf16.f32 "
        "{%0,%1,%2,%3}, {%4,%5,%6,%7}, {%8,%9}, {%0,%1,%2,%3};"
        : "+f"(c[0]), "+f"(c[1]), "+f"(c[2]), "+f"(c[3])
        : "r"(a0), "r"(a1), "r"(a2), "r"(a3), "r"(b0), "r"(b1));
}

#define APITCH 72    /* 72 mod 32 = 8 -> conflict-free A frag LDS */
#define BPITCH 136   /* 136 mod 32 = 8 -> conflict-free B frag LDS */

__global__ __launch_bounds__(256, 2) void k_gemm_tc(
    const float* __restrict__ A_ext, const float* __restrict__ B,
    const float* __restrict__ att_s, const float* __restrict__ att_d,
    int M, int K, int layer)
{
    __shared__ uint32_t AsH[2][8][APITCH];
    __shared__ uint32_t AsL[2][8][APITCH];
    __shared__ uint32_t BsH[2][8][BPITCH];
    __shared__ uint32_t BsL[2][8][BPITCH];

    const float* A = layer ? g_x2 : A_ext;
    float* als = g_als[layer];
    float* ald = g_ald[layer];
    const int NN = FOUT;

    int bm = blockIdx.y * 64;
    int bn = blockIdx.x * 128;
    int tid  = threadIdx.x;
    int lane = tid & 31;
    int warp = tid >> 5;
    int wm = (warp & 1) * 32;    // warp row offset (2 warp-rows)
    int wn = (warp >> 1) * 32;   // warp col offset (4 warp-cols)

    // A tile 64x16 fp32: row = tid>>2, k offset = (tid&3)*4 (one float4)
    int am = tid >> 2;
    int ak = (tid & 3) * 4;
    int arow = bm + am;
    // B tile 16x128 fp32: kpair row = tid>>5, cols (tid&31)*4
    int br = tid >> 5;
    int bc = (tid & 31) * 4;

    float acc[2][4][4];
#pragma unroll
    for (int mi = 0; mi < 2; mi++)
#pragma unroll
        for (int ni = 0; ni < 4; ni++)
#pragma unroll
            for (int r = 0; r < 4; r++) acc[mi][ni][r] = 0.f;

    float4 av, b0v, b1v;
    auto load_tile = [&](int k0) {
        av = (arow < M) ? *(const float4*)(A + (size_t)arow * K + k0 + ak)
                        : make_float4(0.f, 0.f, 0.f, 0.f);
        b0v = *(const float4*)(B + (size_t)(k0 + 2 * br) * NN + bn + bc);
        b1v = *(const float4*)(B + (size_t)(k0 + 2 * br + 1) * NN + bn + bc);
    };
    auto store_tile = [&](int buf) {
        int akp = ak >> 1;   // kpair base: 0,2,4,6
        uint32_t H0, L0, H1, L1;
        split2(av.x, av.y, H0, L0);
        split2(av.z, av.w, H1, L1);
        AsH[buf][akp][am]     = H0;  AsL[buf][akp][am]     = L0;
        AsH[buf][akp + 1][am] = H1;  AsL[buf][akp + 1][am] = L1;
        float ve[4] = {b0v.x, b0v.y, b0v.z, b0v.w};
        float vo[4] = {b1v.x, b1v.y, b1v.z, b1v.w};
        uint32_t BH[4], BL[4];
#pragma unroll
        for (int j = 0; j < 4; j++) split2(ve[j], vo[j], BH[j], BL[j]);
        *(uint4*)&BsH[buf][br][bc] = make_uint4(BH[0], BH[1], BH[2], BH[3]);
        *(uint4*)&BsL[buf][br][bc] = make_uint4(BL[0], BL[1], BL[2], BL[3]);
    };

    load_tile(0);
    store_tile(0);
    __syncthreads();

    int buf = 0;
    for (int k0 = 0; k0 < K; k0 += 16) {
        bool has_next = (k0 + 16) < K;
        if (has_next) load_tile(k0 + 16);

        int fk = lane & 3;
        int fg = lane >> 2;
        uint32_t ah[2][4], al[2][4];
#pragma unroll
        for (int mi = 0; mi < 2; mi++) {
            int m0 = wm + mi * 16 + fg;
            ah[mi][0] = AsH[buf][fk][m0];      ah[mi][1] = AsH[buf][fk][m0 + 8];
            ah[mi][2] = AsH[buf][fk + 4][m0];  ah[mi][3] = AsH[buf][fk + 4][m0 + 8];
            al[mi][0] = AsL[buf][fk][m0];      al[mi][1] = AsL[buf][fk][m0 + 8];
            al[mi][2] = AsL[buf][fk + 4][m0];  al[mi][3] = AsL[buf][fk + 4][m0 + 8];
        }
        uint32_t bh[4][2], bl[4][2];
#pragma unroll
        for (int ni = 0; ni < 4; ni++) {
            int n0 = wn + ni * 8 + fg;
            bh[ni][0] = BsH[buf][fk][n0];      bh[ni][1] = BsH[buf][fk + 4][n0];
            bl[ni][0] = BsL[buf][fk][n0];      bl[ni][1] = BsL[buf][fk + 4][n0];
        }

#pragma unroll
        for (int mi = 0; mi < 2; mi++)
#pragma unroll
            for (int ni = 0; ni < 4; ni++) {
                mma_bf16(acc[mi][ni], ah[mi][0], ah[mi][1], ah[mi][2], ah[mi][3],
                         bh[ni][0], bh[ni][1]);
                mma_bf16(acc[mi][ni], ah[mi][0], ah[mi][1], ah[mi][2], ah[mi][3],
                         bl[ni][0], bl[ni][1]);
                mma_bf16(acc[mi][ni], al[mi][0], al[mi][1], al[mi][2], al[mi][3],
                         bh[ni][0], bh[ni][1]);
            }

        if (has_next) store_tile(buf ^ 1);
        __syncthreads();
        buf ^= 1;
    }

    // ---- epilogue: fp16 store + fused att dot products ----
    int fg = lane >> 2;
    int fk = lane & 3;
    int headg = (bn + wn) >> 6;

    float vsv[4][2], vdv[4][2];
#pragma unroll
    for (int ni = 0; ni < 4; ni++) {
        int c = bn + wn + ni * 8 + fk * 2;
        vsv[ni][0] = att_s[c]; vsv[ni][1] = att_s[c + 1];
        vdv[ni][0] = att_d[c]; vdv[ni][1] = att_d[c + 1];
    }

#pragma unroll
    for (int mi = 0; mi < 2; mi++) {
        int r0 = bm + wm + mi * 16 + fg;
        int r1 = r0 + 8;
        float s0 = 0.f, d0 = 0.f, s1 = 0.f, d1 = 0.f;
#pragma unroll
        for (int ni = 0; ni < 4; ni++) {
            int col = bn + wn + ni * 8 + fk * 2;
            __half2 h01 = __floats2half2_rn(acc[mi][ni][0], acc[mi][ni][1]);
            __half2 h23 = __floats2half2_rn(acc[mi][ni][2], acc[mi][ni][3]);
            if (r0 < M) *(__half2*)(g_hh + (size_t)r0 * NN + col) = h01;
            if (r1 < M) *(__half2*)(g_hh + (size_t)r1 * NN + col) = h23;
            s0 += acc[mi][ni][0] * vsv[ni][0] + acc[mi][ni][1] * vsv[ni][1];
            d0 += acc[mi][ni][0] * vdv[ni][0] + acc[mi][ni][1] * vdv[ni][1];
            s1 += acc[mi][ni][2] * vsv[ni][0] + acc[mi][ni][3] * vsv[ni][1];
            d1 += acc[mi][ni][2] * vdv[ni][0] + acc[mi][ni][3] * vdv[ni][1];
        }
#pragma unroll
        for (int off = 2; off; off >>= 1) {
            s0 += __shfl_xor_sync(0xffffffffu, s0, off);
            d0 += __shfl_xor_sync(0xffffffffu, d0, off);
            s1 += __shfl_xor_sync(0xffffffffu, s1, off);
            d1 += __shfl_xor_sync(0xffffffffu, d1, off);
        }
        if (fk == 0) {
            if (r0 < M) {
                atomicAdd(&als[r0 * HH + headg], s0);
                atomicAdd(&ald[r0 * HH + headg], d0);
            }
            if (r1 < M) {
                atomicAdd(&als[r1 * HH + headg], s1);
                atomicAdd(&ald[r1 * HH + headg], d1);
            }
        }
    }
}

// ------------- fused flash softmax + aggregation ----------------------------
// Phase 1 (cooperative, per 32-edge chunk): thread (lane=tid>>3, w=tid&7)
// computes the raw logit t for (edge lane, head w). als reads are coalesced:
// threads 0..7 read one full 32B als row once (was 8 redundant 4B gathers).
// Phase 2 (per-head warp): flash max/exp + MLP-8 h-row gather, as before.
__global__ void k_fusedagg(const float* __restrict__ bias,
                           float* __restrict__ out_ext, int do_relu, int layer)
{
    __shared__ int   s_src[32];
    __shared__ float s_t[32][9];   // stride 9 (coprime 32) -> conflict-free

    int n = blockIdx.x;
    int tid = threadIdx.x;
    int w = tid >> 5, lane = tid & 31;
    int p_lane = tid >> 3;         // phase-1 edge slot 0..31
    int p_w    = tid & 7;          // phase-1 head 0..7
    float* out = out_ext ? out_ext : g_x2;
    const float* als = g_als[layer];
    int s0 = g_offs[n], s1 = g_offs[n + 1];

    float adw_p = g_ald[layer][n * HH + p_w];   // for phase 1
    float m = -1e30f, ssum = 0.f, accx = 0.f, accy = 0.f;

    for (int base = s0; base < s1; base += 32) {
        // ---- phase 1: cooperative logit computation ----
        int idxp = base + p_lane;
        float t = -1e30f;
        int srcp = 0;
        if (idxp < s1) {
            int2 e2 = g_edge[idxp];
            srcp = e2.x;
            float a = als[srcp * HH + p_w] + adw_p;
            a = (a > 0.f) ? a : NEG * a;   // leaky_relu
            t = a + __int_as_float(e2.y);
        }
        __syncthreads();   // protect smem from previous chunk's readers
        s_t[p_lane][p_w] = t;
        if (p_w == 0) s_src[p_lane] = srcp;
        __syncthreads();

        // ---- phase 2: per-head flash update + gather ----
        float tw = s_t[lane][w];
        int mys = s_src[lane];
        float cm = tw;
#pragma unroll
        for (int o = 16; o; o >>= 1)
            cm = fmaxf(cm, __shfl_xor_sync(0xffffffffu, cm, o));
        float mnew = fmaxf(m, cm);
        float scale = __expf(m - mnew);
        ssum *= scale; accx *= scale; accy *= scale;
        m = mnew;

        float e = __expf(tw - mnew);   // exactly 0 for invalid lanes
        ssum += e;

        int cnt = min(32, s1 - base);
        const __half* hrow_base = g_hh + w * CC + lane * 2;
        for (int jb = 0; jb < cnt; jb += 8) {
            float wv[8];
            float2 hv[8];
#pragma unroll
            for (int u = 0; u < 8; u++) {
                int j = (jb + u) & 31;
                int   s  = __shfl_sync(0xffffffffu, mys, j);
                wv[u]    = __shfl_sync(0xffffffffu, e, j);
                hv[u] = __half22float2(
                    *(const __half2*)(hrow_base + (size_t)s * FOUT));
            }
#pragma unroll
            for (int u = 0; u < 8; u++) {
                accx = fmaf(wv[u], hv[u].x, accx);
                accy = fmaf(wv[u], hv[u].y, accy);
            }
        }
    }
#pragma unroll
    for (int o = 16; o; o >>= 1)
        ssum += __shfl_xor_sync(0xffffffffu, ssum, o);

    float r = 1.f / ssum;
    float2 b = *(const float2*)(bias + w * CC + lane * 2);
    float ox = fmaf(accx, r, b.x);
    float oy = fmaf(accy, r, b.y);
    if (do_relu) { ox = fmaxf(ox, 0.f); oy = fmaxf(oy, 0.f); }
    *(float2*)(out + (size_t)n * FOUT + w * CC + lane * 2) = make_float2(ox, oy);
}

// ---------------- launch -----------------------------------------------------
extern "C" void kernel_launch(void* const* d_in, const int* in_sizes, int n_in,
                              void* d_out, int out_size)
{
    const float* x   = (const float*)d_in[0];
    const int*   ei  = (const int*)  d_in[1];
    const float* ew  = (const float*)d_in[2];
    const float* W1  = (const float*)d_in[3];
    const float* as1 = (const float*)d_in[4];
    const float* ad1 = (const float*)d_in[5];
    const float* b1  = (const float*)d_in[6];
    const float* W2  = (const float*)d_in[7];
    const float* as2 = (const float*)d_in[8];
    const float* ad2 = (const float*)d_in[9];
    const float* b2  = (const float*)d_in[10];
    float* out = (float*)d_out;

    // host-side stream/event setup (once; no device allocations)
    static cudaStream_t s2 = nullptr;
    static cudaEvent_t evFork, evCsr;
    if (!s2) {
        cudaStreamCreateWithFlags(&s2, cudaStreamNonBlocking);
        cudaEventCreateWithFlags(&evFork, cudaEventDisableTiming);
        cudaEventCreateWithFlags(&evCsr, cudaEventDisableTiming);
    }

    // fork: CSR build chain runs concurrently with layer-1 GEMM
    cudaEventRecord(evFork, 0);
    cudaStreamWaitEvent(s2, evFork, 0);
    k_zero_cnt<<<(NNODE + 255) / 256, 256, 0, s2>>>();
    k_hist<<<(ETOT + 255) / 256, 256, 0, s2>>>(ei);
    k_scan<<<1, 1024, 0, s2>>>();
    k_scatter<<<(ETOT + 255) / 256, 256, 0, s2>>>(ei, ew);
    cudaEventRecord(evCsr, s2);

    dim3 ggrid(FOUT / 128, (NNODE + 63) / 64);

    // main stream: zero att accumulators, then layer-1 GEMM
    k_zero_att<<<(NNODE * HH + 255) / 256, 256>>>();
    k_gemm_tc<<<ggrid, 256>>>(x, W1, as1, ad1, NNODE, FIN, 0);

    // join: aggregation needs the CSR
    cudaStreamWaitEvent(0, evCsr, 0);
    k_fusedagg<<<NNODE, 256>>>(b1, nullptr, 1, 0);    // -> g_x2 with ReLU

    // layer 2
    k_gemm_tc<<<ggrid, 256>>>(nullptr, W2, as2, ad2, NNODE, FOUT, 1);
    k_fusedagg<<<NNODE, 256>>>(b2, out, 0, 1);        // -> d_out, no ReLU
}